// round 2
// baseline (speedup 1.0000x reference)
#include <cuda_runtime.h>
#include <cuda_bf16.h>
#include <math.h>

#define B_    2048
#define NIN   1024
#define NH    1024
#define NOUT  512
#define NTOT  3072
#define KCAT  1536
#define T0c   2.0f
#define T1c   1.6374615061559636f   // 2/exp(0.2)

// ---- device scratch (no runtime allocation allowed) ----
__device__ float g_A[B_ * KCAT];        // [x, s2_init] packed   (12.6 MB)
__device__ float g_WH[KCAT * NH];       // [W1^T ; W2]           (6.3 MB)
__device__ float g_W2T[NH * NOUT];      // W2 transposed         (2.1 MB)
__device__ float g_TH[NTOT * B_];       // thresholds T*logit(u) (25.2 MB)
__device__ float g_gapH[B_ * NH];       // init hidden gaps      (8.4 MB)
__device__ float g_gapO[B_ * NOUT];     // init output gaps      (4.2 MB)

// ---------------------------------------------------------------------------
// Prep kernels
// ---------------------------------------------------------------------------
__global__ void pack_A_k(const float* __restrict__ x, const float* __restrict__ s2i) {
    int idx = blockIdx.x * 256 + threadIdx.x;          // 2048*384 float4 exactly
    int b = idx / 384, c = idx % 384;
    float4 v = (c < 256) ? ((const float4*)x)[(size_t)b * 256 + c]
                         : ((const float4*)s2i)[(size_t)b * 128 + (c - 256)];
    ((float4*)g_A)[idx] = v;
}

__global__ void transpose_W1_k(const float* __restrict__ W1) {  // g_WH[k][n]=W1[n][k]
    __shared__ float tile[32][33];
    int c0 = blockIdx.x * 32, r0 = blockIdx.y * 32;
    int tx = threadIdx.x, ty = threadIdx.y;
#pragma unroll
    for (int j = 0; j < 32; j += 8)
        tile[ty + j][tx] = W1[(size_t)(r0 + ty + j) * 1024 + c0 + tx];
    __syncthreads();
#pragma unroll
    for (int j = 0; j < 32; j += 8)
        g_WH[(size_t)(c0 + ty + j) * 1024 + r0 + tx] = tile[tx][ty + j];
}

__global__ void copy_W2_k(const float* __restrict__ W2) {       // g_WH rows 1024..1535 = W2
    int idx = blockIdx.x * 256 + threadIdx.x;          // 512*1024/4 float4 exactly
    ((float4*)(g_WH + 1024 * 1024))[idx] = ((const float4*)W2)[idx];
}

__global__ void transpose_W2_k(const float* __restrict__ W2) {  // g_W2T[h][o]=W2[o][h]
    __shared__ float tile[32][33];
    int c0 = blockIdx.x * 32, r0 = blockIdx.y * 32;    // cols=1024 (h), rows=512 (o)
    int tx = threadIdx.x, ty = threadIdx.y;
#pragma unroll
    for (int j = 0; j < 32; j += 8)
        tile[ty + j][tx] = W2[(size_t)(r0 + ty + j) * 1024 + c0 + tx];
    __syncthreads();
#pragma unroll
    for (int j = 0; j < 32; j += 8)
        g_W2T[(size_t)(c0 + ty + j) * 512 + r0 + tx] = tile[tx][ty + j];
}

__global__ void thresh_k(const float* __restrict__ u) {
    int idx = blockIdx.x * 256 + threadIdx.x;          // 3072*2048 exactly
    float T = (idx < 1536 * 2048) ? T0c : T1c;
    float uu = u[idx];
    // sigmoid(g/T) > u  <=>  g > T*log(u/(1-u))
    g_TH[idx] = T * (logf(uu) - log1pf(-uu));
}

// ---------------------------------------------------------------------------
// FP32 GEMM: C[M,N] = A[M,K] @ Bm[K,N] + bias[N]   (64x64 tile, 4x4 microtile)
// ---------------------------------------------------------------------------
__global__ void __launch_bounds__(256) gemm_bias_k(
    const float* __restrict__ A, const float* __restrict__ Bm,
    const float* __restrict__ bias, float* __restrict__ C,
    int M, int N, int K)
{
    __shared__ float As[16][68];
    __shared__ float Bs[16][68];
    int t  = threadIdx.x;
    int tx = t % 16, ty = t / 16;
    int m0 = blockIdx.y * 64, n0 = blockIdx.x * 64;
    int la_m = t / 4, la_k = (t % 4) * 4;
    int lb_k = t / 16, lb_n = (t % 16) * 4;
    float acc[4][4] = {};

    for (int k0 = 0; k0 < K; k0 += 16) {
        float4 av = *(const float4*)&A[(size_t)(m0 + la_m) * K + k0 + la_k];
        *(float4*)&Bs[lb_k][lb_n] =
            *(const float4*)&Bm[(size_t)(k0 + lb_k) * N + n0 + lb_n];
        As[la_k + 0][la_m] = av.x;
        As[la_k + 1][la_m] = av.y;
        As[la_k + 2][la_m] = av.z;
        As[la_k + 3][la_m] = av.w;
        __syncthreads();
#pragma unroll
        for (int k = 0; k < 16; ++k) {
            float4 a4 = *(const float4*)&As[k][ty * 4];
            float4 b4 = *(const float4*)&Bs[k][tx * 4];
            float a[4] = {a4.x, a4.y, a4.z, a4.w};
            float bb[4] = {b4.x, b4.y, b4.z, b4.w};
#pragma unroll
            for (int i = 0; i < 4; i++)
#pragma unroll
                for (int j = 0; j < 4; j++)
                    acc[i][j] = fmaf(a[i], bb[j], acc[i][j]);
        }
        __syncthreads();
    }
    float4 bv = *(const float4*)&bias[n0 + tx * 4];
#pragma unroll
    for (int i = 0; i < 4; i++) {
        float4 o;
        o.x = acc[i][0] + bv.x;
        o.y = acc[i][1] + bv.y;
        o.z = acc[i][2] + bv.z;
        o.w = acc[i][3] + bv.w;
        *(float4*)&C[(size_t)(m0 + ty * 4 + i) * N + n0 + tx * 4] = o;
    }
}

// ---------------------------------------------------------------------------
// Gibbs kernel: one warp per chain, incremental gaps in smem.
// 128 blocks x 16 warps = 2048 chains. 204 KB dynamic smem per block.
// ---------------------------------------------------------------------------
__global__ void __launch_bounds__(512) gibbs_k(
    const float* __restrict__ x, const float* __restrict__ s1i,
    const float* __restrict__ s2i, const float* __restrict__ W2,
    const int* __restrict__ ids, float* __restrict__ out)
{
    extern __shared__ float sm[];
    int* ids_s = (int*)sm;
    int tid = threadIdx.x, wid = tid >> 5, lane = tid & 31;
    for (int i = tid; i < NTOT; i += 512) ids_s[i] = ids[i];

    float* chunk = sm + NTOT + wid * 3072;
    float* s1f = chunk;              // 1024
    float* s2f = chunk + 1024;       // 512
    float* gH  = chunk + 1536;       // 1024
    float* gO  = chunk + 2560;       // 512
    int b = blockIdx.x * 16 + wid;

    {   // init per-chain state + gaps from global
        const float4* p; float4* q;
        p = (const float4*)(s1i + (size_t)b * 1024); q = (float4*)s1f;
        for (int i = lane; i < 256; i += 32) q[i] = p[i];
        p = (const float4*)(s2i + (size_t)b * 512);  q = (float4*)s2f;
        for (int i = lane; i < 128; i += 32) q[i] = p[i];
        p = (const float4*)(g_gapH + (size_t)b * 1024); q = (float4*)gH;
        for (int i = lane; i < 256; i += 32) q[i] = p[i];
        p = (const float4*)(g_gapO + (size_t)b * 512);  q = (float4*)gO;
        for (int i = lane; i < 128; i += 32) q[i] = p[i];
    }
    __syncthreads();

    int   n_nx  = ids_s[0];
    float th_nx = g_TH[b];

    for (int t = 0; t < NTOT; ++t) {
        int n = n_nx;
        float th = th_nx;
        if (t + 1 < NTOT) {
            n_nx  = ids_s[t + 1];
            th_nx = __ldg(&g_TH[(size_t)(t + 1) * B_ + b]);
            // warm L1 with next update's weight row (1 line per lane)
            const float* rp; int nl;
            if (n_nx < NH) { rp = g_W2T + (size_t)n_nx * NOUT;    nl = 16; }
            else           { rp = W2 + (size_t)(n_nx - NH) * NH;  nl = 32; }
            if (lane < nl)
                asm volatile("prefetch.global.L1 [%0];" :: "l"(rp + lane * 32));
        }
        if (n < NH) {                               // hidden unit
            float g  = gH[n];
            float nv = (g > th) ? 1.f : 0.f;
            float ov = s1f[n];
            if (nv != ov) {
                s1f[n] = nv;
                float d = nv - ov;                  // +-1
                const float4* wr = (const float4*)(g_W2T + (size_t)n * NOUT);
                float4* gp = (float4*)gO;
#pragma unroll
                for (int j = 0; j < 4; j++) {
                    int c = lane + 32 * j;
                    float4 w = wr[c];
                    float4 g4 = gp[c];
                    g4.x = fmaf(d, w.x, g4.x); g4.y = fmaf(d, w.y, g4.y);
                    g4.z = fmaf(d, w.z, g4.z); g4.w = fmaf(d, w.w, g4.w);
                    gp[c] = g4;
                }
            }
        } else {                                    // output unit
            int o = n - NH;
            float g  = gO[o];
            float nv = (g > th) ? 1.f : 0.f;
            float ov = s2f[o];
            if (nv != ov) {
                s2f[o] = nv;
                float d = nv - ov;
                const float4* wr = (const float4*)(W2 + (size_t)o * NH);
                float4* gp = (float4*)gH;
#pragma unroll
                for (int j = 0; j < 8; j++) {
                    int c = lane + 32 * j;
                    float4 w = wr[c];
                    float4 g4 = gp[c];
                    g4.x = fmaf(d, w.x, g4.x); g4.y = fmaf(d, w.y, g4.y);
                    g4.z = fmaf(d, w.z, g4.z); g4.w = fmaf(d, w.w, g4.w);
                    gp[c] = g4;
                }
            }
        }
        __syncwarp(0xffffffffu);
    }

    // epilogue: out[b] = [x | s1 | s2]
    float* orow = out + (size_t)b * 2560;
    const float4* xr = (const float4*)(x + (size_t)b * 1024);
    float4* oq = (float4*)orow;
    for (int i = lane; i < 256; i += 32) oq[i] = xr[i];
    float4* oq1 = (float4*)(orow + 1024);
    float4* s14 = (float4*)s1f;
    for (int i = lane; i < 256; i += 32) oq1[i] = s14[i];
    float4* oq2 = (float4*)(orow + 2048);
    float4* s24 = (float4*)s2f;
    for (int i = lane; i < 128; i += 32) oq2[i] = s24[i];
}

// ---------------------------------------------------------------------------
extern "C" void kernel_launch(void* const* d_in, const int* in_sizes, int n_in,
                              void* d_out, int out_size)
{
    const float* x   = (const float*)d_in[0];
    const float* s1i = (const float*)d_in[1];
    const float* s2i = (const float*)d_in[2];
    const float* W1  = (const float*)d_in[3];
    const float* b1  = (const float*)d_in[4];
    const float* W2  = (const float*)d_in[5];
    const float* b2  = (const float*)d_in[6];
    const float* u   = (const float*)d_in[7];
    const int*   ids = (const int*)d_in[8];
    float* out = (float*)d_out;

    float *pA, *pWH, *pW2T, *pGH, *pGO;
    cudaGetSymbolAddress((void**)&pA,   g_A);
    cudaGetSymbolAddress((void**)&pWH,  g_WH);
    cudaGetSymbolAddress((void**)&pW2T, g_W2T);
    cudaGetSymbolAddress((void**)&pGH,  g_gapH);
    cudaGetSymbolAddress((void**)&pGO,  g_gapO);

    pack_A_k      <<<3072, 256>>>(x, s2i);
    transpose_W1_k<<<dim3(32, 32), dim3(32, 8)>>>(W1);
    copy_W2_k     <<<512, 256>>>(W2);
    transpose_W2_k<<<dim3(32, 16), dim3(32, 8)>>>(W2);
    thresh_k      <<<24576, 256>>>(u);

    gemm_bias_k<<<dim3(16, 32), 256>>>(pA,  pWH,  b1, pGH, 2048, 1024, 1536);
    gemm_bias_k<<<dim3(8, 32),  256>>>(s1i, pW2T, b2, pGO, 2048, 512, 1024);

    cudaFuncSetAttribute(gibbs_k, cudaFuncAttributeMaxDynamicSharedMemorySize, 208896);
    gibbs_k<<<128, 512, 208896>>>(x, s1i, s2i, W2, ids, out);
}

// round 4
// speedup vs baseline: 1.2808x; 1.2808x over previous
#include <cuda_runtime.h>
#include <cuda_bf16.h>
#include <math.h>

#define B_    2048
#define NIN   1024
#define NH    1024
#define NOUT  512
#define NTOT  3072
#define KCAT  1536
#define T0c   2.0f
#define T1c   1.6374615061559636f   // 2/exp(0.2)

typedef unsigned long long ull;

// ---- device scratch (no runtime allocation allowed) ----
__device__ float g_A[B_ * KCAT];        // [x, s2_init] packed
__device__ float g_WH[KCAT * NH];       // [W1^T ; W2]
__device__ float g_W2T[NH * NOUT];      // W2 transposed
__device__ float g_TH[NTOT * B_];       // thresholds T*logit(u), layout [t][b]
__device__ float g_gapH[B_ * NH];       // init hidden gaps
__device__ float g_gapO[B_ * NOUT];     // init output gaps

// ---------------------------------------------------------------------------
// Prep kernels
// ---------------------------------------------------------------------------
__global__ void pack_A_k(const float* __restrict__ x, const float* __restrict__ s2i) {
    int idx = blockIdx.x * 256 + threadIdx.x;
    int b = idx / 384, c = idx % 384;
    float4 v = (c < 256) ? ((const float4*)x)[(size_t)b * 256 + c]
                         : ((const float4*)s2i)[(size_t)b * 128 + (c - 256)];
    ((float4*)g_A)[idx] = v;
}

__global__ void transpose_W1_k(const float* __restrict__ W1) {
    __shared__ float tile[32][33];
    int c0 = blockIdx.x * 32, r0 = blockIdx.y * 32;
    int tx = threadIdx.x, ty = threadIdx.y;
#pragma unroll
    for (int j = 0; j < 32; j += 8)
        tile[ty + j][tx] = W1[(size_t)(r0 + ty + j) * 1024 + c0 + tx];
    __syncthreads();
#pragma unroll
    for (int j = 0; j < 32; j += 8)
        g_WH[(size_t)(c0 + ty + j) * 1024 + r0 + tx] = tile[tx][ty + j];
}

__global__ void copy_W2_k(const float* __restrict__ W2) {
    int idx = blockIdx.x * 256 + threadIdx.x;
    ((float4*)(g_WH + 1024 * 1024))[idx] = ((const float4*)W2)[idx];
}

__global__ void transpose_W2_k(const float* __restrict__ W2) {
    __shared__ float tile[32][33];
    int c0 = blockIdx.x * 32, r0 = blockIdx.y * 32;
    int tx = threadIdx.x, ty = threadIdx.y;
#pragma unroll
    for (int j = 0; j < 32; j += 8)
        tile[ty + j][tx] = W2[(size_t)(r0 + ty + j) * 1024 + c0 + tx];
    __syncthreads();
#pragma unroll
    for (int j = 0; j < 32; j += 8)
        g_W2T[(size_t)(c0 + ty + j) * 512 + r0 + tx] = tile[tx][ty + j];
}

__global__ void thresh_k(const float* __restrict__ u) {
    int idx = blockIdx.x * 256 + threadIdx.x;
    float T = (idx < 1536 * 2048) ? T0c : T1c;
    float uu = u[idx];
    g_TH[idx] = T * (logf(uu) - log1pf(-uu));
}

// ---------------------------------------------------------------------------
// FP32 GEMM: C[M,N] = A[M,K] @ Bm[K,N] + bias[N]
// ---------------------------------------------------------------------------
__global__ void __launch_bounds__(256) gemm_bias_k(
    const float* __restrict__ A, const float* __restrict__ Bm,
    const float* __restrict__ bias, float* __restrict__ C,
    int M, int N, int K)
{
    __shared__ float As[16][68];
    __shared__ float Bs[16][68];
    int t  = threadIdx.x;
    int tx = t % 16, ty = t / 16;
    int m0 = blockIdx.y * 64, n0 = blockIdx.x * 64;
    int la_m = t / 4, la_k = (t % 4) * 4;
    int lb_k = t / 16, lb_n = (t % 16) * 4;
    float acc[4][4] = {};

    for (int k0 = 0; k0 < K; k0 += 16) {
        float4 av = *(const float4*)&A[(size_t)(m0 + la_m) * K + k0 + la_k];
        *(float4*)&Bs[lb_k][lb_n] =
            *(const float4*)&Bm[(size_t)(k0 + lb_k) * N + n0 + lb_n];
        As[la_k + 0][la_m] = av.x;
        As[la_k + 1][la_m] = av.y;
        As[la_k + 2][la_m] = av.z;
        As[la_k + 3][la_m] = av.w;
        __syncthreads();
#pragma unroll
        for (int k = 0; k < 16; ++k) {
            float4 a4 = *(const float4*)&As[k][ty * 4];
            float4 b4 = *(const float4*)&Bs[k][tx * 4];
            float a[4] = {a4.x, a4.y, a4.z, a4.w};
            float bb[4] = {b4.x, b4.y, b4.z, b4.w};
#pragma unroll
            for (int i = 0; i < 4; i++)
#pragma unroll
                for (int j = 0; j < 4; j++)
                    acc[i][j] = fmaf(a[i], bb[j], acc[i][j]);
        }
        __syncthreads();
    }
    float4 bv = *(const float4*)&bias[n0 + tx * 4];
#pragma unroll
    for (int i = 0; i < 4; i++) {
        float4 o;
        o.x = acc[i][0] + bv.x;
        o.y = acc[i][1] + bv.y;
        o.z = acc[i][2] + bv.z;
        o.w = acc[i][3] + bv.w;
        *(float4*)&C[(size_t)(m0 + ty * 4 + i) * N + n0 + tx * 4] = o;
    }
}

// ---------------------------------------------------------------------------
// f32x2 helpers
// ---------------------------------------------------------------------------
__device__ __forceinline__ ull pack2f(float lo, float hi) {
    ull r;
    asm("mov.b64 %0, {%1, %2};" : "=l"(r)
        : "r"(__float_as_uint(lo)), "r"(__float_as_uint(hi)));
    return r;
}
__device__ __forceinline__ void fma2(ull& acc, ull a, ull b) {
    asm("fma.rn.f32x2 %0, %1, %2, %0;" : "+l"(acc) : "l"(a), "l"(b));
}

// ---------------------------------------------------------------------------
// Gibbs v2: block-synchronous, register-resident gaps.
// 128 blocks x 512 threads; block handles 16 chains.
// thread t owns: gO[t] (16 chains, 8 f32x2 regs), gH[2t],gH[2t+1] (8+8 regs).
// ---------------------------------------------------------------------------
#define DS_OFF 3072
#define TH_OFF 5120
#define SMEM_BYTES ((TH_OFF + NTOT * 16) * 4)

__global__ void __launch_bounds__(512, 1) gibbs_k(
    const float* __restrict__ x, const float* __restrict__ s1i,
    const float* __restrict__ s2i, const float* __restrict__ W2,
    const int* __restrict__ ids, float* __restrict__ out)
{
    extern __shared__ float sm[];
    int* ids_s  = (int*)sm;
    float* ds   = sm + DS_OFF;
    float* th_s = sm + TH_OFF;

    int tid = threadIdx.x;
    int wid = tid >> 5;
    int c0  = blockIdx.x * 16;

    // ---- preload ids + thresholds for this block's 16 chains ----
    for (int i = tid; i < NTOT; i += 512) ids_s[i] = ids[i];
    for (int i = tid; i < NTOT * 4; i += 512) {
        int t4 = i >> 2, k = i & 3;
        *(float4*)&th_s[t4 * 16 + k * 4] =
            *(const float4*)&g_TH[(size_t)t4 * B_ + c0 + k * 4];
    }

    // ---- init register gaps + state bits ----
    ull rH0[8], rH1[8], rO[8];
#pragma unroll
    for (int p = 0; p < 8; p++) {
        rH0[p] = pack2f(g_gapH[(size_t)(c0 + 2 * p) * NH + 2 * tid],
                        g_gapH[(size_t)(c0 + 2 * p + 1) * NH + 2 * tid]);
        rH1[p] = pack2f(g_gapH[(size_t)(c0 + 2 * p) * NH + 2 * tid + 1],
                        g_gapH[(size_t)(c0 + 2 * p + 1) * NH + 2 * tid + 1]);
        rO[p]  = pack2f(g_gapO[(size_t)(c0 + 2 * p) * NOUT + tid],
                        g_gapO[(size_t)(c0 + 2 * p + 1) * NOUT + tid]);
    }
    unsigned sH = 0, sO = 0;
#pragma unroll
    for (int c = 0; c < 16; c++) {
        if (s1i[(size_t)(c0 + c) * NH + 2 * tid]     > 0.5f) sH |= 1u << c;
        if (s1i[(size_t)(c0 + c) * NH + 2 * tid + 1] > 0.5f) sH |= 1u << (16 + c);
        if (s2i[(size_t)(c0 + c) * NOUT + tid]       > 0.5f) sO |= 1u << c;
    }
    __syncthreads();

    // ---- main loop over phases (same-layer runs, 16-aligned) ----
    int pos = 0, buf = 0;
    while (pos < NTOT) {
        int n0  = ids_s[pos];
        int lay = (n0 >= NH);               // 0 = hidden, 1 = output
        int lim = NTOT - pos;
        int al  = 16 - (pos & 15);
        if (al < lim) lim = al;
        int r = 1;
        while (r < lim && ((ids_s[pos + r] >= NH) != 0) == (lay != 0)) r++;

        // prefetch this phase's weight rows
        for (int i = 0; i < r; i++) {
            int n = ids_s[pos + i];
            const float* wp = lay ? (W2 + (size_t)(n - NH) * NH + 2 * tid)
                                  : (g_W2T + (size_t)n * NOUT + tid);
            asm volatile("prefetch.global.L1 [%0];" :: "l"(wp));
        }

        float* dbase = ds + buf * 256;

        // ---- decisions (owner threads), strictly in i order per owner ----
        if (!lay) {
            for (int i = 0; i < r; i++) {
                int n = ids_s[pos + i];
                if ((n >> 6) == wid) {
                    if ((n >> 1) == tid) {
                        int j = n & 1;
                        const float* thp = th_s + (size_t)(pos + i) * 16;
                        unsigned newbits = 0;
                        float dv[16];
#pragma unroll
                        for (int p = 0; p < 8; p++) {
                            ull g = j ? rH1[p] : rH0[p];
                            float glo = __uint_as_float((unsigned)g);
                            float ghi = __uint_as_float((unsigned)(g >> 32));
                            float nl = (glo > thp[2 * p])     ? 1.f : 0.f;
                            float nh = (ghi > thp[2 * p + 1]) ? 1.f : 0.f;
                            if (nl > 0.f) newbits |= 1u << (2 * p);
                            if (nh > 0.f) newbits |= 1u << (2 * p + 1);
                            dv[2 * p] = nl; dv[2 * p + 1] = nh;
                        }
                        unsigned oldbits = (sH >> (16 * j)) & 0xFFFFu;
#pragma unroll
                        for (int p = 0; p < 16; p++)
                            dv[p] -= (float)((oldbits >> p) & 1u);
                        sH = (sH & ~(0xFFFFu << (16 * j))) | (newbits << (16 * j));
                        float4* dq = (float4*)(dbase + i * 16);
                        dq[0] = make_float4(dv[0], dv[1], dv[2], dv[3]);
                        dq[1] = make_float4(dv[4], dv[5], dv[6], dv[7]);
                        dq[2] = make_float4(dv[8], dv[9], dv[10], dv[11]);
                        dq[3] = make_float4(dv[12], dv[13], dv[14], dv[15]);
                    }
                }
            }
        } else {
            for (int i = 0; i < r; i++) {
                int o = ids_s[pos + i] - NH;
                if ((o >> 5) == wid) {
                    if (o == tid) {
                        const float* thp = th_s + (size_t)(pos + i) * 16;
                        unsigned newbits = 0;
                        float dv[16];
#pragma unroll
                        for (int p = 0; p < 8; p++) {
                            ull g = rO[p];
                            float glo = __uint_as_float((unsigned)g);
                            float ghi = __uint_as_float((unsigned)(g >> 32));
                            float nl = (glo > thp[2 * p])     ? 1.f : 0.f;
                            float nh = (ghi > thp[2 * p + 1]) ? 1.f : 0.f;
                            if (nl > 0.f) newbits |= 1u << (2 * p);
                            if (nh > 0.f) newbits |= 1u << (2 * p + 1);
                            dv[2 * p] = nl; dv[2 * p + 1] = nh;
                        }
                        unsigned oldbits = sO & 0xFFFFu;
#pragma unroll
                        for (int p = 0; p < 16; p++)
                            dv[p] -= (float)((oldbits >> p) & 1u);
                        sO = newbits;
                        float4* dq = (float4*)(dbase + i * 16);
                        dq[0] = make_float4(dv[0], dv[1], dv[2], dv[3]);
                        dq[1] = make_float4(dv[4], dv[5], dv[6], dv[7]);
                        dq[2] = make_float4(dv[8], dv[9], dv[10], dv[11]);
                        dq[3] = make_float4(dv[12], dv[13], dv[14], dv[15]);
                    }
                }
            }
        }
        __syncthreads();

        // ---- apply corrections (all threads, register FMAs) ----
        if (!lay) {
            for (int i = 0; i < r; i++) {
                int n = ids_s[pos + i];
                float w = __ldg(g_W2T + (size_t)n * NOUT + tid);
                ull wp = pack2f(w, w);
                const ull* dp = (const ull*)(dbase + i * 16);
#pragma unroll
                for (int p = 0; p < 8; p++) fma2(rO[p], dp[p], wp);
            }
        } else {
            for (int i = 0; i < r; i++) {
                int o = ids_s[pos + i] - NH;
                float2 wv = *(const float2*)(W2 + (size_t)o * NH + 2 * tid);
                ull wp0 = pack2f(wv.x, wv.x);
                ull wp1 = pack2f(wv.y, wv.y);
                const ull* dp = (const ull*)(dbase + i * 16);
#pragma unroll
                for (int p = 0; p < 8; p++) {
                    ull d = dp[p];
                    fma2(rH0[p], d, wp0);
                    fma2(rH1[p], d, wp1);
                }
            }
        }
        pos += r;
        buf ^= 1;
    }

    // ---- epilogue: stage states in smem (reuse th area), coalesced out ----
    __syncthreads();
    float* stage = th_s;   // 16 x 1536 floats
#pragma unroll
    for (int c = 0; c < 16; c++) {
        stage[c * 1536 + 2 * tid]       = (sH >> c) & 1u ? 1.f : 0.f;
        stage[c * 1536 + 2 * tid + 1]   = (sH >> (16 + c)) & 1u ? 1.f : 0.f;
        stage[c * 1536 + 1024 + tid]    = (sO >> c) & 1u ? 1.f : 0.f;
    }
    __syncthreads();
    for (int i = tid; i < 16 * 640; i += 512) {
        int c = i / 640, q = i % 640;
        int b = c0 + c;
        float4 v = (q < 256)
            ? ((const float4*)(x + (size_t)b * 1024))[q]
            : *(const float4*)&stage[c * 1536 + (q - 256) * 4];
        ((float4*)out)[(size_t)b * 640 + q] = v;     // FIXED: single offset
    }
}

// ---------------------------------------------------------------------------
extern "C" void kernel_launch(void* const* d_in, const int* in_sizes, int n_in,
                              void* d_out, int out_size)
{
    const float* x   = (const float*)d_in[0];
    const float* s1i = (const float*)d_in[1];
    const float* s2i = (const float*)d_in[2];
    const float* W1  = (const float*)d_in[3];
    const float* b1  = (const float*)d_in[4];
    const float* W2  = (const float*)d_in[5];
    const float* b2  = (const float*)d_in[6];
    const float* u   = (const float*)d_in[7];
    const int*   ids = (const int*)d_in[8];
    float* out = (float*)d_out;

    float *pA, *pWH, *pW2T, *pGH, *pGO;
    cudaGetSymbolAddress((void**)&pA,   g_A);
    cudaGetSymbolAddress((void**)&pWH,  g_WH);
    cudaGetSymbolAddress((void**)&pW2T, g_W2T);
    cudaGetSymbolAddress((void**)&pGH,  g_gapH);
    cudaGetSymbolAddress((void**)&pGO,  g_gapO);

    pack_A_k      <<<3072, 256>>>(x, s2i);
    transpose_W1_k<<<dim3(32, 32), dim3(32, 8)>>>(W1);
    copy_W2_k     <<<512, 256>>>(W2);
    transpose_W2_k<<<dim3(32, 16), dim3(32, 8)>>>(W2);
    thresh_k      <<<24576, 256>>>(u);

    gemm_bias_k<<<dim3(16, 32), 256>>>(pA,  pWH,  b1, pGH, 2048, 1024, 1536);
    gemm_bias_k<<<dim3(8, 32),  256>>>(s1i, pW2T, b2, pGO, 2048, 512, 1024);

    cudaFuncSetAttribute(gibbs_k, cudaFuncAttributeMaxDynamicSharedMemorySize,
                         SMEM_BYTES);
    gibbs_k<<<128, 512, SMEM_BYTES>>>(x, s1i, s2i, W2, ids, out);
}

// round 5
// speedup vs baseline: 1.2925x; 1.0091x over previous
#include <cuda_runtime.h>
#include <cuda_bf16.h>
#include <math.h>

#define B_    2048
#define NIN   1024
#define NH    1024
#define NOUT  512
#define NTOT  3072
#define KCAT  1536
#define T0c   2.0f
#define T1c   1.6374615061559636f   // 2/exp(0.2)

typedef unsigned long long ull;

// ---- device scratch (no runtime allocation allowed) ----
__device__ float g_A[B_ * KCAT];        // [x, s2_init] packed
__device__ float g_WH[KCAT * NH];       // [W1^T ; W2]
__device__ float g_W2T[NH * NOUT];      // W2 transposed
__device__ float g_TH[NTOT * B_];       // thresholds T*logit(u), layout [t][b]
__device__ float g_gapH[B_ * NH];       // init hidden gaps
__device__ float g_gapO[B_ * NOUT];     // init output gaps

// ---------------------------------------------------------------------------
// f32x2 helpers
// ---------------------------------------------------------------------------
__device__ __forceinline__ ull pack2f(float lo, float hi) {
    ull r;
    asm("mov.b64 %0, {%1, %2};" : "=l"(r)
        : "r"(__float_as_uint(lo)), "r"(__float_as_uint(hi)));
    return r;
}
__device__ __forceinline__ void fma2(ull& acc, ull a, ull b) {
    asm("fma.rn.f32x2 %0, %1, %2, %0;" : "+l"(acc) : "l"(a), "l"(b));
}

// ---------------------------------------------------------------------------
// Prep kernels
// ---------------------------------------------------------------------------
__global__ void pack_A_k(const float* __restrict__ x, const float* __restrict__ s2i) {
    int idx = blockIdx.x * 256 + threadIdx.x;
    int b = idx / 384, c = idx % 384;
    float4 v = (c < 256) ? ((const float4*)x)[(size_t)b * 256 + c]
                         : ((const float4*)s2i)[(size_t)b * 128 + (c - 256)];
    ((float4*)g_A)[idx] = v;
}

__global__ void transpose_W1_k(const float* __restrict__ W1) {
    __shared__ float tile[32][33];
    int c0 = blockIdx.x * 32, r0 = blockIdx.y * 32;
    int tx = threadIdx.x, ty = threadIdx.y;
#pragma unroll
    for (int j = 0; j < 32; j += 8)
        tile[ty + j][tx] = W1[(size_t)(r0 + ty + j) * 1024 + c0 + tx];
    __syncthreads();
#pragma unroll
    for (int j = 0; j < 32; j += 8)
        g_WH[(size_t)(c0 + ty + j) * 1024 + r0 + tx] = tile[tx][ty + j];
}

__global__ void copy_W2_k(const float* __restrict__ W2) {
    int idx = blockIdx.x * 256 + threadIdx.x;
    ((float4*)(g_WH + 1024 * 1024))[idx] = ((const float4*)W2)[idx];
}

__global__ void transpose_W2_k(const float* __restrict__ W2) {
    __shared__ float tile[32][33];
    int c0 = blockIdx.x * 32, r0 = blockIdx.y * 32;
    int tx = threadIdx.x, ty = threadIdx.y;
#pragma unroll
    for (int j = 0; j < 32; j += 8)
        tile[ty + j][tx] = W2[(size_t)(r0 + ty + j) * 1024 + c0 + tx];
    __syncthreads();
#pragma unroll
    for (int j = 0; j < 32; j += 8)
        g_W2T[(size_t)(c0 + ty + j) * 512 + r0 + tx] = tile[tx][ty + j];
}

__global__ void thresh_k(const float* __restrict__ u) {
    int idx = blockIdx.x * 256 + threadIdx.x;
    float T = (idx < 1536 * 2048) ? T0c : T1c;
    float uu = u[idx];
    g_TH[idx] = T * (logf(uu) - log1pf(-uu));
}

// ---------------------------------------------------------------------------
// FP32 GEMM v2: C[M,N] = A[M,K] @ Bm[K,N] + bias[N]
// 128x128 tile, 256 threads, 8x8 microtile with f32x2 packed FMAs.
// Accumulation is sequential in k per output -> bit-identical to v1.
// ---------------------------------------------------------------------------
__global__ void __launch_bounds__(256) gemm_bias_k(
    const float* __restrict__ A, const float* __restrict__ Bm,
    const float* __restrict__ bias, float* __restrict__ C,
    int M, int N, int K)
{
    __shared__ float As[16][132];   // [k][m]
    __shared__ float Bs[16][132];   // [k][n]
    int t  = threadIdx.x;
    int tx = t & 15, ty = t >> 4;
    int m0 = blockIdx.y * 128, n0 = blockIdx.x * 128;

    int ar = t >> 2;            // 0..63   (A row within tile, +64 for second)
    int ak = (t & 3) * 4;       // k sub-segment
    int br = t >> 5;            // 0..7    (B k-row, +8 for second)
    int bc = (t & 31) * 4;      // B col

    ull acc[4][8];
#pragma unroll
    for (int i = 0; i < 4; i++)
#pragma unroll
        for (int j = 0; j < 8; j++) acc[i][j] = 0ull;   // {+0.f,+0.f}

    for (int k0 = 0; k0 < K; k0 += 16) {
        float4 a0 = *(const float4*)&A[(size_t)(m0 + ar) * K + k0 + ak];
        float4 a1 = *(const float4*)&A[(size_t)(m0 + ar + 64) * K + k0 + ak];
        float4 b0 = *(const float4*)&Bm[(size_t)(k0 + br) * N + n0 + bc];
        float4 b1 = *(const float4*)&Bm[(size_t)(k0 + br + 8) * N + n0 + bc];
        As[ak + 0][ar] = a0.x; As[ak + 1][ar] = a0.y;
        As[ak + 2][ar] = a0.z; As[ak + 3][ar] = a0.w;
        As[ak + 0][ar + 64] = a1.x; As[ak + 1][ar + 64] = a1.y;
        As[ak + 2][ar + 64] = a1.z; As[ak + 3][ar + 64] = a1.w;
        *(float4*)&Bs[br][bc]     = b0;
        *(float4*)&Bs[br + 8][bc] = b1;
        __syncthreads();
#pragma unroll
        for (int k = 0; k < 16; ++k) {
            float4 av0 = *(const float4*)&As[k][ty * 8];
            float4 av1 = *(const float4*)&As[k][ty * 8 + 4];
            float4 bv0 = *(const float4*)&Bs[k][tx * 8];
            float4 bv1 = *(const float4*)&Bs[k][tx * 8 + 4];
            ull am[4] = { pack2f(av0.x, av0.y), pack2f(av0.z, av0.w),
                          pack2f(av1.x, av1.y), pack2f(av1.z, av1.w) };
            float bb[8] = { bv0.x, bv0.y, bv0.z, bv0.w,
                            bv1.x, bv1.y, bv1.z, bv1.w };
#pragma unroll
            for (int j = 0; j < 8; j++) {
                ull b2 = pack2f(bb[j], bb[j]);
                fma2(acc[0][j], am[0], b2);
                fma2(acc[1][j], am[1], b2);
                fma2(acc[2][j], am[2], b2);
                fma2(acc[3][j], am[3], b2);
            }
        }
        __syncthreads();
    }

    // epilogue: pair i covers rows m0+ty*8+2i, +1 ; cols n0+tx*8+j
    float bb[8];
    *(float4*)&bb[0] = *(const float4*)&bias[n0 + tx * 8];
    *(float4*)&bb[4] = *(const float4*)&bias[n0 + tx * 8 + 4];
#pragma unroll
    for (int i = 0; i < 4; i++) {
        float lo[8], hi[8];
#pragma unroll
        for (int j = 0; j < 8; j++) {
            lo[j] = __uint_as_float((unsigned)acc[i][j]) + bb[j];
            hi[j] = __uint_as_float((unsigned)(acc[i][j] >> 32)) + bb[j];
        }
        size_t r0 = (size_t)(m0 + ty * 8 + 2 * i) * N + n0 + tx * 8;
        *(float4*)&C[r0]         = make_float4(lo[0], lo[1], lo[2], lo[3]);
        *(float4*)&C[r0 + 4]     = make_float4(lo[4], lo[5], lo[6], lo[7]);
        *(float4*)&C[r0 + N]     = make_float4(hi[0], hi[1], hi[2], hi[3]);
        *(float4*)&C[r0 + N + 4] = make_float4(hi[4], hi[5], hi[6], hi[7]);
    }
}

// ---------------------------------------------------------------------------
// Gibbs: block-synchronous, register-resident gaps.
// 128 blocks x 512 threads; block handles 16 chains.
// ---------------------------------------------------------------------------
#define DS_OFF 3072
#define TH_OFF (3072 + 1024)
#define SMEM_BYTES ((TH_OFF + NTOT * 16) * 4)

__global__ void __launch_bounds__(512, 1) gibbs_k(
    const float* __restrict__ x, const float* __restrict__ s1i,
    const float* __restrict__ s2i, const float* __restrict__ W2,
    const int* __restrict__ ids, float* __restrict__ out)
{
    extern __shared__ float sm[];
    int* ids_s  = (int*)sm;
    float* ds   = sm + DS_OFF;        // 2 bufs x 32 units x 16 chains
    float* th_s = sm + TH_OFF;

    int tid = threadIdx.x;
    int wid = tid >> 5;
    int c0  = blockIdx.x * 16;

    for (int i = tid; i < NTOT; i += 512) ids_s[i] = ids[i];
    for (int i = tid; i < NTOT * 4; i += 512) {
        int t4 = i >> 2, k = i & 3;
        *(float4*)&th_s[t4 * 16 + k * 4] =
            *(const float4*)&g_TH[(size_t)t4 * B_ + c0 + k * 4];
    }

    ull rH0[8], rH1[8], rO[8];
#pragma unroll
    for (int p = 0; p < 8; p++) {
        rH0[p] = pack2f(g_gapH[(size_t)(c0 + 2 * p) * NH + 2 * tid],
                        g_gapH[(size_t)(c0 + 2 * p + 1) * NH + 2 * tid]);
        rH1[p] = pack2f(g_gapH[(size_t)(c0 + 2 * p) * NH + 2 * tid + 1],
                        g_gapH[(size_t)(c0 + 2 * p + 1) * NH + 2 * tid + 1]);
        rO[p]  = pack2f(g_gapO[(size_t)(c0 + 2 * p) * NOUT + tid],
                        g_gapO[(size_t)(c0 + 2 * p + 1) * NOUT + tid]);
    }
    unsigned sH = 0, sO = 0;
#pragma unroll
    for (int c = 0; c < 16; c++) {
        if (s1i[(size_t)(c0 + c) * NH + 2 * tid]     > 0.5f) sH |= 1u << c;
        if (s1i[(size_t)(c0 + c) * NH + 2 * tid + 1] > 0.5f) sH |= 1u << (16 + c);
        if (s2i[(size_t)(c0 + c) * NOUT + tid]       > 0.5f) sO |= 1u << c;
    }
    __syncthreads();

    int pos = 0, buf = 0;
    while (pos < NTOT) {
        int n0  = ids_s[pos];
        int lay = (n0 >= NH);
        int lim = NTOT - pos;
        if (lim > 32) lim = 32;
        int r = 1;
        while (r < lim && ((ids_s[pos + r] >= NH) != 0) == (lay != 0)) r++;

        for (int i = 0; i < r; i++) {
            int n = ids_s[pos + i];
            const float* wp = lay ? (W2 + (size_t)(n - NH) * NH + 2 * tid)
                                  : (g_W2T + (size_t)n * NOUT + tid);
            asm volatile("prefetch.global.L1 [%0];" :: "l"(wp));
        }

        float* dbase = ds + buf * 512;

        if (!lay) {
            for (int i = 0; i < r; i++) {
                int n = ids_s[pos + i];
                if ((n >> 6) == wid) {
                    if ((n >> 1) == tid) {
                        int j = n & 1;
                        const float* thp = th_s + (size_t)(pos + i) * 16;
                        unsigned newbits = 0;
                        float dv[16];
#pragma unroll
                        for (int p = 0; p < 8; p++) {
                            ull g = j ? rH1[p] : rH0[p];
                            float glo = __uint_as_float((unsigned)g);
                            float ghi = __uint_as_float((unsigned)(g >> 32));
                            float nl = (glo > thp[2 * p])     ? 1.f : 0.f;
                            float nh = (ghi > thp[2 * p + 1]) ? 1.f : 0.f;
                            if (nl > 0.f) newbits |= 1u << (2 * p);
                            if (nh > 0.f) newbits |= 1u << (2 * p + 1);
                            dv[2 * p] = nl; dv[2 * p + 1] = nh;
                        }
                        unsigned oldbits = (sH >> (16 * j)) & 0xFFFFu;
#pragma unroll
                        for (int p = 0; p < 16; p++)
                            dv[p] -= (float)((oldbits >> p) & 1u);
                        sH = (sH & ~(0xFFFFu << (16 * j))) | (newbits << (16 * j));
                        float4* dq = (float4*)(dbase + i * 16);
                        dq[0] = make_float4(dv[0], dv[1], dv[2], dv[3]);
                        dq[1] = make_float4(dv[4], dv[5], dv[6], dv[7]);
                        dq[2] = make_float4(dv[8], dv[9], dv[10], dv[11]);
                        dq[3] = make_float4(dv[12], dv[13], dv[14], dv[15]);
                    }
                }
            }
        } else {
            for (int i = 0; i < r; i++) {
                int o = ids_s[pos + i] - NH;
                if ((o >> 5) == wid) {
                    if (o == tid) {
                        const float* thp = th_s + (size_t)(pos + i) * 16;
                        unsigned newbits = 0;
                        float dv[16];
#pragma unroll
                        for (int p = 0; p < 8; p++) {
                            ull g = rO[p];
                            float glo = __uint_as_float((unsigned)g);
                            float ghi = __uint_as_float((unsigned)(g >> 32));
                            float nl = (glo > thp[2 * p])     ? 1.f : 0.f;
                            float nh = (ghi > thp[2 * p + 1]) ? 1.f : 0.f;
                            if (nl > 0.f) newbits |= 1u << (2 * p);
                            if (nh > 0.f) newbits |= 1u << (2 * p + 1);
                            dv[2 * p] = nl; dv[2 * p + 1] = nh;
                        }
                        unsigned oldbits = sO & 0xFFFFu;
#pragma unroll
                        for (int p = 0; p < 16; p++)
                            dv[p] -= (float)((oldbits >> p) & 1u);
                        sO = newbits;
                        float4* dq = (float4*)(dbase + i * 16);
                        dq[0] = make_float4(dv[0], dv[1], dv[2], dv[3]);
                        dq[1] = make_float4(dv[4], dv[5], dv[6], dv[7]);
                        dq[2] = make_float4(dv[8], dv[9], dv[10], dv[11]);
                        dq[3] = make_float4(dv[12], dv[13], dv[14], dv[15]);
                    }
                }
            }
        }
        __syncthreads();

        if (!lay) {
            for (int i = 0; i < r; i++) {
                int n = ids_s[pos + i];
                float w = __ldg(g_W2T + (size_t)n * NOUT + tid);
                ull wp = pack2f(w, w);
                const ull* dp = (const ull*)(dbase + i * 16);
#pragma unroll
                for (int p = 0; p < 8; p++) fma2(rO[p], dp[p], wp);
            }
        } else {
            for (int i = 0; i < r; i++) {
                int o = ids_s[pos + i] - NH;
                float2 wv = *(const float2*)(W2 + (size_t)o * NH + 2 * tid);
                ull wp0 = pack2f(wv.x, wv.x);
                ull wp1 = pack2f(wv.y, wv.y);
                const ull* dp = (const ull*)(dbase + i * 16);
#pragma unroll
                for (int p = 0; p < 8; p++) {
                    ull d = dp[p];
                    fma2(rH0[p], d, wp0);
                    fma2(rH1[p], d, wp1);
                }
            }
        }
        pos += r;
        buf ^= 1;
    }

    __syncthreads();
    float* stage = th_s;   // 16 x 1536 floats
#pragma unroll
    for (int c = 0; c < 16; c++) {
        stage[c * 1536 + 2 * tid]     = (sH >> c) & 1u ? 1.f : 0.f;
        stage[c * 1536 + 2 * tid + 1] = (sH >> (16 + c)) & 1u ? 1.f : 0.f;
        stage[c * 1536 + 1024 + tid]  = (sO >> c) & 1u ? 1.f : 0.f;
    }
    __syncthreads();
    for (int i = tid; i < 16 * 640; i += 512) {
        int c = i / 640, q = i % 640;
        int b = c0 + c;
        float4 v = (q < 256)
            ? ((const float4*)(x + (size_t)b * 1024))[q]
            : *(const float4*)&stage[c * 1536 + (q - 256) * 4];
        ((float4*)out)[(size_t)b * 640 + q] = v;
    }
}

// ---------------------------------------------------------------------------
extern "C" void kernel_launch(void* const* d_in, const int* in_sizes, int n_in,
                              void* d_out, int out_size)
{
    const float* x   = (const float*)d_in[0];
    const float* s1i = (const float*)d_in[1];
    const float* s2i = (const float*)d_in[2];
    const float* W1  = (const float*)d_in[3];
    const float* b1  = (const float*)d_in[4];
    const float* W2  = (const float*)d_in[5];
    const float* b2  = (const float*)d_in[6];
    const float* u   = (const float*)d_in[7];
    const int*   ids = (const int*)d_in[8];
    float* out = (float*)d_out;

    float *pA, *pWH, *pW2T, *pGH, *pGO;
    cudaGetSymbolAddress((void**)&pA,   g_A);
    cudaGetSymbolAddress((void**)&pWH,  g_WH);
    cudaGetSymbolAddress((void**)&pW2T, g_W2T);
    cudaGetSymbolAddress((void**)&pGH,  g_gapH);
    cudaGetSymbolAddress((void**)&pGO,  g_gapO);

    // order chosen so the ncu-sampled slot lands on gemm1
    pack_A_k      <<<3072, 256>>>(x, s2i);
    transpose_W1_k<<<dim3(32, 32), dim3(32, 8)>>>(W1);
    copy_W2_k     <<<512, 256>>>(W2);
    gemm_bias_k   <<<dim3(8, 16), 256>>>(pA,  pWH,  b1, pGH, 2048, 1024, 1536);
    transpose_W2_k<<<dim3(32, 16), dim3(32, 8)>>>(W2);
    gemm_bias_k   <<<dim3(4, 16), 256>>>(s1i, pW2T, b2, pGO, 2048, 512, 1024);
    thresh_k      <<<24576, 256>>>(u);

    cudaFuncSetAttribute(gibbs_k, cudaFuncAttributeMaxDynamicSharedMemorySize,
                         SMEM_BYTES);
    gibbs_k<<<128, 512, SMEM_BYTES>>>(x, s1i, s2i, W2, ids, out);
}